// round 7
// baseline (speedup 1.0000x reference)
#include <cuda_runtime.h>
#include <math.h>

// Problem constants
#define BATCH 8
#define SEQ 256
#define DMODEL 256
#define NHEADS 8
#define HDIM 32
#define ROWS (BATCH * SEQ)     // 2048

// Scratch (device globals — no allocation allowed)
__device__ float g_Qh[BATCH * NHEADS * SEQ * HDIM]; // [b,h,l,d]
__device__ float g_Kh[BATCH * NHEADS * SEQ * HDIM];
__device__ float g_Vh[BATCH * NHEADS * SEQ * HDIM];

// ---------------------------------------------------------------------------
// Tiled GEMM body (round-3 proven layout): C[i][j] = sum_k X[i][k]*W[j][k]+b[j]
// CTA tile 64x64, 256 threads, thread tile 4x4, K-tile 32, smem stride 33
// (2-way conflicts only). Stores into head-split [b,h,l,d] layout.
// ---------------------------------------------------------------------------
__global__ __launch_bounds__(256) void gemm_proj3(
    const float* __restrict__ Q, const float* __restrict__ K,
    const float* __restrict__ V,
    const float* __restrict__ Wq, const float* __restrict__ bq,
    const float* __restrict__ Wk, const float* __restrict__ bk,
    const float* __restrict__ Wv, const float* __restrict__ bv,
    float* __restrict__ oQ, float* __restrict__ oK, float* __restrict__ oV)
{
    const float *X, *W, *bias;
    float* out;
    if (blockIdx.z == 0)      { X = Q; W = Wq; bias = bq; out = oQ; }
    else if (blockIdx.z == 1) { X = K; W = Wk; bias = bk; out = oK; }
    else                      { X = V; W = Wv; bias = bv; out = oV; }

    __shared__ float Xs[64][33];
    __shared__ float Ws[64][33];

    const int i0 = blockIdx.x * 64;
    const int j0 = blockIdx.y * 64;
    const int tid = threadIdx.x;
    const int tx = tid & 15;   // j direction
    const int ty = tid >> 4;   // i direction

    float acc[4][4];
#pragma unroll
    for (int m = 0; m < 4; m++)
#pragma unroll
        for (int n = 0; n < 4; n++) acc[m][n] = 0.f;

    for (int k0 = 0; k0 < DMODEL; k0 += 32) {
#pragma unroll
        for (int i = tid; i < 64 * 32; i += 256) {
            int r = i >> 5, c = i & 31;
            Xs[r][c] = X[(size_t)(i0 + r) * DMODEL + k0 + c];
            Ws[r][c] = W[(size_t)(j0 + r) * DMODEL + k0 + c];
        }
        __syncthreads();
#pragma unroll
        for (int kk = 0; kk < 32; kk++) {
            float xr[4], wr[4];
#pragma unroll
            for (int m = 0; m < 4; m++) xr[m] = Xs[ty * 4 + m][kk];
#pragma unroll
            for (int n = 0; n < 4; n++) wr[n] = Ws[tx * 4 + n][kk];
#pragma unroll
            for (int m = 0; m < 4; m++)
#pragma unroll
                for (int n = 0; n < 4; n++)
                    acc[m][n] = fmaf(xr[m], wr[n], acc[m][n]);
        }
        __syncthreads();
    }

#pragma unroll
    for (int m = 0; m < 4; m++) {
#pragma unroll
        for (int n = 0; n < 4; n++) {
            int i = i0 + ty * 4 + m;
            int j = j0 + tx * 4 + n;
            float v = acc[m][n] + bias[j];
            int b = i >> 8, q = i & 255;
            int h = j >> 5, d = j & 31;
            out[((size_t)((b * NHEADS + h) * SEQ + q)) * HDIM + d] = v;
        }
    }
}

// ---------------------------------------------------------------------------
// Attention + fused Wo epilogue: 1 CTA per (b,q). 8 warps, warp h = head h.
// Streams tK[b,q,:,:] / tV[b,q,:,:] (256 KB each) once, coalesced, evict-first.
// Attention output row (256 floats) goes to smem; then each thread j computes
// out[bq][j] = bo[j] + sum_d ao[d] * Wo[j][d]  (Wo stays L2/L1 resident).
// ---------------------------------------------------------------------------
__global__ __launch_bounds__(256) void attn_kernel(
    const float* __restrict__ tK, const float* __restrict__ tV,
    const float* __restrict__ Wo, const float* __restrict__ bo,
    float* __restrict__ out)
{
    __shared__ float sc[NHEADS][SEQ];   // per-head scores / attention weights
    __shared__ float ao[DMODEL];        // attention output row

    const int bq = blockIdx.x;          // b*256 + q
    const int b = bq >> 8;
    const int q = bq & 255;
    const int tid = threadIdx.x;
    const int h = tid >> 5;
    const int lane = tid & 31;
    const int kk = lane >> 3;           // 0..3
    const int dq = lane & 7;            // 0..7

    const float* __restrict__ tKb = tK + (size_t)bq * (SEQ * DMODEL);
    const float* __restrict__ tVb = tV + (size_t)bq * (SEQ * DMODEL);
    const float* __restrict__ KhB = g_Kh + (size_t)(b * NHEADS + h) * (SEQ * HDIM);
    const float* __restrict__ VhB = g_Vh + (size_t)(b * NHEADS + h) * (SEQ * HDIM);

    const float4 q4 = *(const float4*)(g_Qh +
        (size_t)((b * NHEADS + h) * SEQ + q) * HDIM + dq * 4);
    const float scale = 0.17677669529663687f;  // 1/sqrt(32)

    // ---- scores[k] = scale * q . (Kh[k] + tK[k]) ----
#pragma unroll 8
    for (int k0 = 0; k0 < SEQ; k0 += 4) {
        int k = k0 + kk;
        float4 t4 = __ldcs((const float4*)(tKb + (size_t)k * DMODEL + h * HDIM + dq * 4));
        float4 k4 = *(const float4*)(KhB + k * HDIM + dq * 4);
        float s = (t4.x + k4.x) * q4.x + (t4.y + k4.y) * q4.y
                + (t4.z + k4.z) * q4.z + (t4.w + k4.w) * q4.w;
        s += __shfl_xor_sync(0xffffffffu, s, 1);
        s += __shfl_xor_sync(0xffffffffu, s, 2);
        s += __shfl_xor_sync(0xffffffffu, s, 4);
        if (dq == 0) sc[h][k] = s * scale;
    }
    __syncwarp();

    // ---- softmax over k (per warp/head) ----
    float m = -1e30f;
#pragma unroll
    for (int i = lane; i < SEQ; i += 32) m = fmaxf(m, sc[h][i]);
#pragma unroll
    for (int o = 16; o; o >>= 1) m = fmaxf(m, __shfl_xor_sync(0xffffffffu, m, o));
    float sum = 0.f;
#pragma unroll
    for (int i = lane; i < SEQ; i += 32) {
        float e = __expf(sc[h][i] - m);
        sc[h][i] = e;
        sum += e;
    }
#pragma unroll
    for (int o = 16; o; o >>= 1) sum += __shfl_xor_sync(0xffffffffu, sum, o);
    const float inv = 1.f / sum;
#pragma unroll
    for (int i = lane; i < SEQ; i += 32) sc[h][i] *= inv;
    __syncwarp();

    // ---- ao[d] = sum_k attn[k] * (Vh[k][d] + tV[k][d]) ----
    float4 acc = make_float4(0.f, 0.f, 0.f, 0.f);
#pragma unroll 8
    for (int k0 = 0; k0 < SEQ; k0 += 4) {
        int k = k0 + kk;
        float a = sc[h][k];
        float4 v4 = *(const float4*)(VhB + k * HDIM + dq * 4);
        float4 t4 = __ldcs((const float4*)(tVb + (size_t)k * DMODEL + h * HDIM + dq * 4));
        acc.x = fmaf(a, v4.x + t4.x, acc.x);
        acc.y = fmaf(a, v4.y + t4.y, acc.y);
        acc.z = fmaf(a, v4.z + t4.z, acc.z);
        acc.w = fmaf(a, v4.w + t4.w, acc.w);
    }
    // combine the 4 kk-groups (lanes dq, 8+dq, 16+dq, 24+dq)
    acc.x += __shfl_xor_sync(0xffffffffu, acc.x, 8);
    acc.y += __shfl_xor_sync(0xffffffffu, acc.y, 8);
    acc.z += __shfl_xor_sync(0xffffffffu, acc.z, 8);
    acc.w += __shfl_xor_sync(0xffffffffu, acc.w, 8);
    acc.x += __shfl_xor_sync(0xffffffffu, acc.x, 16);
    acc.y += __shfl_xor_sync(0xffffffffu, acc.y, 16);
    acc.z += __shfl_xor_sync(0xffffffffu, acc.z, 16);
    acc.w += __shfl_xor_sync(0xffffffffu, acc.w, 16);

    if (kk == 0) {
        *(float4*)(&ao[h * HDIM + dq * 4]) = acc;
    }
    __syncthreads();

    // ---- fused output projection: out[j] = bo[j] + sum_d ao[d]*Wo[j][d] ----
    {
        const int j = tid;
        const float* __restrict__ wrow = Wo + (size_t)j * DMODEL;
        float r = bo[j];
#pragma unroll 8
        for (int d = 0; d < DMODEL; d += 4) {
            float4 w4 = *(const float4*)(wrow + d);   // L2/L1 resident
            // ao[d..d+3] is a broadcast read across the CTA
            r = fmaf(ao[d + 0], w4.x, r);
            r = fmaf(ao[d + 1], w4.y, r);
            r = fmaf(ao[d + 2], w4.z, r);
            r = fmaf(ao[d + 3], w4.w, r);
        }
        out[(size_t)bq * DMODEL + j] = r;
    }
}

// ---------------------------------------------------------------------------
// Launch: fused QKV projection -> attention(+Wo epilogue). Single stream,
// no allocation, no sync — graph-capturable.
// ---------------------------------------------------------------------------
extern "C" void kernel_launch(void* const* d_in, const int* in_sizes, int n_in,
                              void* d_out, int out_size)
{
    const float* Q  = (const float*)d_in[0];
    const float* K  = (const float*)d_in[1];
    const float* V  = (const float*)d_in[2];
    const float* tK = (const float*)d_in[3];
    const float* tV = (const float*)d_in[4];
    const float* Wq = (const float*)d_in[5];
    const float* bq = (const float*)d_in[6];
    const float* Wk = (const float*)d_in[7];
    const float* bk = (const float*)d_in[8];
    const float* Wv = (const float*)d_in[9];
    const float* bv = (const float*)d_in[10];
    const float* Wo = (const float*)d_in[11];
    const float* bo = (const float*)d_in[12];
    float* out = (float*)d_out;

    float *gQh, *gKh, *gVh;
    cudaGetSymbolAddress((void**)&gQh, g_Qh);
    cudaGetSymbolAddress((void**)&gKh, g_Kh);
    cudaGetSymbolAddress((void**)&gVh, g_Vh);

    dim3 pgrid(ROWS / 64, DMODEL / 64, 3);
    gemm_proj3<<<pgrid, 256>>>(Q, K, V, Wq, bq, Wk, bk, Wv, bv, gQh, gKh, gVh);

    attn_kernel<<<ROWS, 256>>>(tK, tV, Wo, bo, out);
}

// round 8
// speedup vs baseline: 1.3002x; 1.3002x over previous
#include <cuda_runtime.h>
#include <math.h>

// Problem constants
#define BATCH 8
#define SEQ 256
#define DMODEL 256
#define NHEADS 8
#define HDIM 32
#define ROWS (BATCH * SEQ)     // 2048

// Scratch (device globals — no allocation allowed)
__device__ float g_Qh[BATCH * NHEADS * SEQ * HDIM]; // [b,h,l,d]
__device__ float g_Kh[BATCH * NHEADS * SEQ * HDIM];
__device__ float g_Vh[BATCH * NHEADS * SEQ * HDIM];
__device__ float g_AO[ROWS * DMODEL];               // attention output, [b*l, dmodel]

// ---------------------------------------------------------------------------
// Tiled GEMM body (round-3 proven layout): C[i][j] = sum_k X[i][k]*W[j][k]+b[j]
// CTA tile 64x64, 256 threads, thread tile 4x4, K-tile 32, smem stride 33.
// ---------------------------------------------------------------------------
__device__ __forceinline__ void gemm_body(
    const float* __restrict__ X, const float* __restrict__ W,
    const float* __restrict__ bias, float* __restrict__ out,
    int i0, int j0, int headsplit)
{
    __shared__ float Xs[64][33];
    __shared__ float Ws[64][33];

    const int tid = threadIdx.x;
    const int tx = tid & 15;   // j direction
    const int ty = tid >> 4;   // i direction

    float acc[4][4];
#pragma unroll
    for (int m = 0; m < 4; m++)
#pragma unroll
        for (int n = 0; n < 4; n++) acc[m][n] = 0.f;

    for (int k0 = 0; k0 < DMODEL; k0 += 32) {
#pragma unroll
        for (int i = tid; i < 64 * 32; i += 256) {
            int r = i >> 5, c = i & 31;
            Xs[r][c] = X[(size_t)(i0 + r) * DMODEL + k0 + c];
            Ws[r][c] = W[(size_t)(j0 + r) * DMODEL + k0 + c];
        }
        __syncthreads();
#pragma unroll
        for (int kk = 0; kk < 32; kk++) {
            float xr[4], wr[4];
#pragma unroll
            for (int m = 0; m < 4; m++) xr[m] = Xs[ty * 4 + m][kk];
#pragma unroll
            for (int n = 0; n < 4; n++) wr[n] = Ws[tx * 4 + n][kk];
#pragma unroll
            for (int m = 0; m < 4; m++)
#pragma unroll
                for (int n = 0; n < 4; n++)
                    acc[m][n] = fmaf(xr[m], wr[n], acc[m][n]);
        }
        __syncthreads();
    }

#pragma unroll
    for (int m = 0; m < 4; m++) {
#pragma unroll
        for (int n = 0; n < 4; n++) {
            int i = i0 + ty * 4 + m;
            int j = j0 + tx * 4 + n;
            float v = acc[m][n] + bias[j];
            if (headsplit) {
                int b = i >> 8, q = i & 255;
                int h = j >> 5, d = j & 31;
                out[((size_t)((b * NHEADS + h) * SEQ + q)) * HDIM + d] = v;
            } else {
                out[(size_t)i * DMODEL + j] = v;
            }
        }
    }
}

// Fused Q/K/V projection: blockIdx.z selects the projection (one wave, 384 CTAs).
__global__ __launch_bounds__(256) void gemm_proj3(
    const float* __restrict__ Q, const float* __restrict__ K,
    const float* __restrict__ V,
    const float* __restrict__ Wq, const float* __restrict__ bq,
    const float* __restrict__ Wk, const float* __restrict__ bk,
    const float* __restrict__ Wv, const float* __restrict__ bv,
    float* __restrict__ oQ, float* __restrict__ oK, float* __restrict__ oV)
{
    const float *X, *W, *bias;
    float* out;
    if (blockIdx.z == 0)      { X = Q; W = Wq; bias = bq; out = oQ; }
    else if (blockIdx.z == 1) { X = K; W = Wk; bias = bk; out = oK; }
    else                      { X = V; W = Wv; bias = bv; out = oV; }
    gemm_body(X, W, bias, out, blockIdx.x * 64, blockIdx.y * 64, 1);
}

// Output projection: out = AO @ Wo^T + bo
__global__ __launch_bounds__(256) void gemm_out(
    const float* __restrict__ X, const float* __restrict__ W,
    const float* __restrict__ bias, float* __restrict__ out)
{
    gemm_body(X, W, bias, out, blockIdx.x * 64, blockIdx.y * 64, 0);
}

// ---------------------------------------------------------------------------
// Attention kernel (exact round-3 version: 32 regs, occ ~85%, DRAM ~80%).
// 1 CTA per (b,q). 8 warps, warp h handles head h. Streams tK/tV once.
// ---------------------------------------------------------------------------
__global__ __launch_bounds__(256) void attn_kernel(
    const float* __restrict__ tK, const float* __restrict__ tV)
{
    __shared__ float sc[NHEADS][SEQ];   // per-head scores / attention weights

    const int bq = blockIdx.x;          // b*256 + q
    const int b = bq >> 8;
    const int q = bq & 255;
    const int tid = threadIdx.x;
    const int h = tid >> 5;
    const int lane = tid & 31;
    const int kk = lane >> 3;           // 0..3
    const int dq = lane & 7;            // 0..7

    const float* __restrict__ tKb = tK + (size_t)bq * (SEQ * DMODEL);
    const float* __restrict__ tVb = tV + (size_t)bq * (SEQ * DMODEL);
    const float* __restrict__ KhB = g_Kh + (size_t)(b * NHEADS + h) * (SEQ * HDIM);
    const float* __restrict__ VhB = g_Vh + (size_t)(b * NHEADS + h) * (SEQ * HDIM);

    const float4 q4 = *(const float4*)(g_Qh +
        (size_t)((b * NHEADS + h) * SEQ + q) * HDIM + dq * 4);
    const float scale = 0.17677669529663687f;  // 1/sqrt(32)

    // ---- scores[k] = scale * q . (Kh[k] + tK[k]) ----
#pragma unroll 4
    for (int k0 = 0; k0 < SEQ; k0 += 4) {
        int k = k0 + kk;
        float4 t4 = *(const float4*)(tKb + (size_t)k * DMODEL + h * HDIM + dq * 4);
        float4 k4 = *(const float4*)(KhB + k * HDIM + dq * 4);
        float s = (t4.x + k4.x) * q4.x + (t4.y + k4.y) * q4.y
                + (t4.z + k4.z) * q4.z + (t4.w + k4.w) * q4.w;
        s += __shfl_xor_sync(0xffffffffu, s, 1);
        s += __shfl_xor_sync(0xffffffffu, s, 2);
        s += __shfl_xor_sync(0xffffffffu, s, 4);
        if (dq == 0) sc[h][k] = s * scale;
    }
    __syncwarp();

    // ---- softmax over k (per warp/head) ----
    float m = -1e30f;
#pragma unroll
    for (int i = lane; i < SEQ; i += 32) m = fmaxf(m, sc[h][i]);
#pragma unroll
    for (int o = 16; o; o >>= 1) m = fmaxf(m, __shfl_xor_sync(0xffffffffu, m, o));
    float sum = 0.f;
#pragma unroll
    for (int i = lane; i < SEQ; i += 32) {
        float e = __expf(sc[h][i] - m);
        sc[h][i] = e;
        sum += e;
    }
#pragma unroll
    for (int o = 16; o; o >>= 1) sum += __shfl_xor_sync(0xffffffffu, sum, o);
    const float inv = 1.f / sum;
#pragma unroll
    for (int i = lane; i < SEQ; i += 32) sc[h][i] *= inv;
    __syncwarp();

    // ---- out[d] = sum_k attn[k] * (Vh[k][d] + tV[k][d]) ----
    float4 acc = make_float4(0.f, 0.f, 0.f, 0.f);
#pragma unroll 4
    for (int k0 = 0; k0 < SEQ; k0 += 4) {
        int k = k0 + kk;
        float a = sc[h][k];
        float4 v4 = *(const float4*)(VhB + k * HDIM + dq * 4);
        float4 t4 = *(const float4*)(tVb + (size_t)k * DMODEL + h * HDIM + dq * 4);
        acc.x = fmaf(a, v4.x + t4.x, acc.x);
        acc.y = fmaf(a, v4.y + t4.y, acc.y);
        acc.z = fmaf(a, v4.z + t4.z, acc.z);
        acc.w = fmaf(a, v4.w + t4.w, acc.w);
    }
    // combine the 4 kk-groups (lanes dq, 8+dq, 16+dq, 24+dq)
    acc.x += __shfl_xor_sync(0xffffffffu, acc.x, 8);
    acc.y += __shfl_xor_sync(0xffffffffu, acc.y, 8);
    acc.z += __shfl_xor_sync(0xffffffffu, acc.z, 8);
    acc.w += __shfl_xor_sync(0xffffffffu, acc.w, 8);
    acc.x += __shfl_xor_sync(0xffffffffu, acc.x, 16);
    acc.y += __shfl_xor_sync(0xffffffffu, acc.y, 16);
    acc.z += __shfl_xor_sync(0xffffffffu, acc.z, 16);
    acc.w += __shfl_xor_sync(0xffffffffu, acc.w, 16);

    if (kk == 0) {
        *(float4*)(g_AO + (size_t)bq * DMODEL + h * HDIM + dq * 4) = acc;
    }
}

// ---------------------------------------------------------------------------
// Launch: fused QKV projection -> attention -> output GEMM. Single stream,
// no allocation, no sync — graph-capturable.
// ---------------------------------------------------------------------------
extern "C" void kernel_launch(void* const* d_in, const int* in_sizes, int n_in,
                              void* d_out, int out_size)
{
    const float* Q  = (const float*)d_in[0];
    const float* K  = (const float*)d_in[1];
    const float* V  = (const float*)d_in[2];
    const float* tK = (const float*)d_in[3];
    const float* tV = (const float*)d_in[4];
    const float* Wq = (const float*)d_in[5];
    const float* bq = (const float*)d_in[6];
    const float* Wk = (const float*)d_in[7];
    const float* bk = (const float*)d_in[8];
    const float* Wv = (const float*)d_in[9];
    const float* bv = (const float*)d_in[10];
    const float* Wo = (const float*)d_in[11];
    const float* bo = (const float*)d_in[12];
    float* out = (float*)d_out;

    float *gQh, *gKh, *gVh, *gAO;
    cudaGetSymbolAddress((void**)&gQh, g_Qh);
    cudaGetSymbolAddress((void**)&gKh, g_Kh);
    cudaGetSymbolAddress((void**)&gVh, g_Vh);
    cudaGetSymbolAddress((void**)&gAO, g_AO);

    dim3 pgrid(ROWS / 64, DMODEL / 64, 3);
    gemm_proj3<<<pgrid, 256>>>(Q, K, V, Wq, bq, Wk, bk, Wv, bv, gQh, gKh, gVh);

    attn_kernel<<<ROWS, 256>>>(tK, tV);

    dim3 ogrid(ROWS / 64, DMODEL / 64);
    gemm_out<<<ogrid, 256>>>(gAO, Wo, bo, out);
}

// round 11
// speedup vs baseline: 1.4351x; 1.1037x over previous
#include <cuda_runtime.h>
#include <math.h>

// Problem constants
#define BATCH 8
#define SEQ 256
#define DMODEL 256
#define NHEADS 8
#define HDIM 32
#define ROWS (BATCH * SEQ)     // 2048

// Scratch (device globals — no allocation allowed)
__device__ float g_Qh[BATCH * NHEADS * SEQ * HDIM]; // [b,h,l,d]
__device__ float g_Kh[BATCH * NHEADS * SEQ * HDIM];
__device__ float g_Vh[BATCH * NHEADS * SEQ * HDIM];
__device__ float g_AO[ROWS * DMODEL];               // attention output, [b*l, dmodel]

// ---------------------------------------------------------------------------
// Fused Q/K/V projection (R7-proven form): blockIdx.z selects the projection.
// CTA tile 64x64, 256 threads, thread tile 4x4, K-tile 32, smem stride 33.
// Body is written directly in the kernel; head-split store is hard-coded.
// ---------------------------------------------------------------------------
__global__ __launch_bounds__(256) void gemm_proj3(
    const float* __restrict__ Q, const float* __restrict__ K,
    const float* __restrict__ V,
    const float* __restrict__ Wq, const float* __restrict__ bq,
    const float* __restrict__ Wk, const float* __restrict__ bk,
    const float* __restrict__ Wv, const float* __restrict__ bv,
    float* __restrict__ oQ, float* __restrict__ oK, float* __restrict__ oV)
{
    const float *X, *W, *bias;
    float* out;
    if (blockIdx.z == 0)      { X = Q; W = Wq; bias = bq; out = oQ; }
    else if (blockIdx.z == 1) { X = K; W = Wk; bias = bk; out = oK; }
    else                      { X = V; W = Wv; bias = bv; out = oV; }

    __shared__ float Xs[64][33];
    __shared__ float Ws[64][33];

    const int i0 = blockIdx.x * 64;
    const int j0 = blockIdx.y * 64;
    const int tid = threadIdx.x;
    const int tx = tid & 15;   // j direction
    const int ty = tid >> 4;   // i direction

    float acc[4][4];
#pragma unroll
    for (int m = 0; m < 4; m++)
#pragma unroll
        for (int n = 0; n < 4; n++) acc[m][n] = 0.f;

    for (int k0 = 0; k0 < DMODEL; k0 += 32) {
#pragma unroll
        for (int i = tid; i < 64 * 32; i += 256) {
            int r = i >> 5, c = i & 31;
            Xs[r][c] = X[(size_t)(i0 + r) * DMODEL + k0 + c];
            Ws[r][c] = W[(size_t)(j0 + r) * DMODEL + k0 + c];
        }
        __syncthreads();
#pragma unroll
        for (int kk = 0; kk < 32; kk++) {
            float xr[4], wr[4];
#pragma unroll
            for (int m = 0; m < 4; m++) xr[m] = Xs[ty * 4 + m][kk];
#pragma unroll
            for (int n = 0; n < 4; n++) wr[n] = Ws[tx * 4 + n][kk];
#pragma unroll
            for (int m = 0; m < 4; m++)
#pragma unroll
                for (int n = 0; n < 4; n++)
                    acc[m][n] = fmaf(xr[m], wr[n], acc[m][n]);
        }
        __syncthreads();
    }

#pragma unroll
    for (int m = 0; m < 4; m++) {
#pragma unroll
        for (int n = 0; n < 4; n++) {
            int i = i0 + ty * 4 + m;
            int j = j0 + tx * 4 + n;
            float v = acc[m][n] + bias[j];
            int b = i >> 8, q = i & 255;
            int h = j >> 5, d = j & 31;
            out[((size_t)((b * NHEADS + h) * SEQ + q)) * HDIM + d] = v;
        }
    }
}

// ---------------------------------------------------------------------------
// Output projection: out = AO @ Wo^T + bo. Own inline body, plain [i][j] store.
// ---------------------------------------------------------------------------
__global__ __launch_bounds__(256) void gemm_out(
    const float* __restrict__ X, const float* __restrict__ W,
    const float* __restrict__ bias, float* __restrict__ out)
{
    __shared__ float Xs[64][33];
    __shared__ float Ws[64][33];

    const int i0 = blockIdx.x * 64;
    const int j0 = blockIdx.y * 64;
    const int tid = threadIdx.x;
    const int tx = tid & 15;   // j direction
    const int ty = tid >> 4;   // i direction

    float acc[4][4];
#pragma unroll
    for (int m = 0; m < 4; m++)
#pragma unroll
        for (int n = 0; n < 4; n++) acc[m][n] = 0.f;

    for (int k0 = 0; k0 < DMODEL; k0 += 32) {
#pragma unroll
        for (int i = tid; i < 64 * 32; i += 256) {
            int r = i >> 5, c = i & 31;
            Xs[r][c] = X[(size_t)(i0 + r) * DMODEL + k0 + c];
            Ws[r][c] = W[(size_t)(j0 + r) * DMODEL + k0 + c];
        }
        __syncthreads();
#pragma unroll
        for (int kk = 0; kk < 32; kk++) {
            float xr[4], wr[4];
#pragma unroll
            for (int m = 0; m < 4; m++) xr[m] = Xs[ty * 4 + m][kk];
#pragma unroll
            for (int n = 0; n < 4; n++) wr[n] = Ws[tx * 4 + n][kk];
#pragma unroll
            for (int m = 0; m < 4; m++)
#pragma unroll
                for (int n = 0; n < 4; n++)
                    acc[m][n] = fmaf(xr[m], wr[n], acc[m][n]);
        }
        __syncthreads();
    }

#pragma unroll
    for (int m = 0; m < 4; m++) {
#pragma unroll
        for (int n = 0; n < 4; n++) {
            int i = i0 + ty * 4 + m;
            int j = j0 + tx * 4 + n;
            out[(size_t)i * DMODEL + j] = acc[m][n] + bias[j];
        }
    }
}

// ---------------------------------------------------------------------------
// Attention kernel (R3-proven: 32 regs, occ ~85%, DRAM ~80%).
// 1 CTA per (b,q). 8 warps, warp h handles head h. Streams tK/tV once.
// ---------------------------------------------------------------------------
__global__ __launch_bounds__(256) void attn_kernel(
    const float* __restrict__ tK, const float* __restrict__ tV)
{
    __shared__ float sc[NHEADS][SEQ];   // per-head scores / attention weights

    const int bq = blockIdx.x;          // b*256 + q
    const int b = bq >> 8;
    const int q = bq & 255;
    const int tid = threadIdx.x;
    const int h = tid >> 5;
    const int lane = tid & 31;
    const int kk = lane >> 3;           // 0..3
    const int dq = lane & 7;            // 0..7

    const float* __restrict__ tKb = tK + (size_t)bq * (SEQ * DMODEL);
    const float* __restrict__ tVb = tV + (size_t)bq * (SEQ * DMODEL);
    const float* __restrict__ KhB = g_Kh + (size_t)(b * NHEADS + h) * (SEQ * HDIM);
    const float* __restrict__ VhB = g_Vh + (size_t)(b * NHEADS + h) * (SEQ * HDIM);

    const float4 q4 = *(const float4*)(g_Qh +
        (size_t)((b * NHEADS + h) * SEQ + q) * HDIM + dq * 4);
    const float scale = 0.17677669529663687f;  // 1/sqrt(32)

    // ---- scores[k] = scale * q . (Kh[k] + tK[k]) ----
#pragma unroll 4
    for (int k0 = 0; k0 < SEQ; k0 += 4) {
        int k = k0 + kk;
        float4 t4 = *(const float4*)(tKb + (size_t)k * DMODEL + h * HDIM + dq * 4);
        float4 k4 = *(const float4*)(KhB + k * HDIM + dq * 4);
        float s = (t4.x + k4.x) * q4.x + (t4.y + k4.y) * q4.y
                + (t4.z + k4.z) * q4.z + (t4.w + k4.w) * q4.w;
        s += __shfl_xor_sync(0xffffffffu, s, 1);
        s += __shfl_xor_sync(0xffffffffu, s, 2);
        s += __shfl_xor_sync(0xffffffffu, s, 4);
        if (dq == 0) sc[h][k] = s * scale;
    }
    __syncwarp();

    // ---- softmax over k (per warp/head) ----
    float m = -1e30f;
#pragma unroll
    for (int i = lane; i < SEQ; i += 32) m = fmaxf(m, sc[h][i]);
#pragma unroll
    for (int o = 16; o; o >>= 1) m = fmaxf(m, __shfl_xor_sync(0xffffffffu, m, o));
    float sum = 0.f;
#pragma unroll
    for (int i = lane; i < SEQ; i += 32) {
        float e = __expf(sc[h][i] - m);
        sc[h][i] = e;
        sum += e;
    }
#pragma unroll
    for (int o = 16; o; o >>= 1) sum += __shfl_xor_sync(0xffffffffu, sum, o);
    const float inv = 1.f / sum;
#pragma unroll
    for (int i = lane; i < SEQ; i += 32) sc[h][i] *= inv;
    __syncwarp();

    // ---- out[d] = sum_k attn[k] * (Vh[k][d] + tV[k][d]) ----
    float4 acc = make_float4(0.f, 0.f, 0.f, 0.f);
#pragma unroll 4
    for (int k0 = 0; k0 < SEQ; k0 += 4) {
        int k = k0 + kk;
        float a = sc[h][k];
        float4 v4 = *(const float4*)(VhB + k * HDIM + dq * 4);
        float4 t4 = *(const float4*)(tVb + (size_t)k * DMODEL + h * HDIM + dq * 4);
        acc.x = fmaf(a, v4.x + t4.x, acc.x);
        acc.y = fmaf(a, v4.y + t4.y, acc.y);
        acc.z = fmaf(a, v4.z + t4.z, acc.z);
        acc.w = fmaf(a, v4.w + t4.w, acc.w);
    }
    // combine the 4 kk-groups (lanes dq, 8+dq, 16+dq, 24+dq)
    acc.x += __shfl_xor_sync(0xffffffffu, acc.x, 8);
    acc.y += __shfl_xor_sync(0xffffffffu, acc.y, 8);
    acc.z += __shfl_xor_sync(0xffffffffu, acc.z, 8);
    acc.w += __shfl_xor_sync(0xffffffffu, acc.w, 8);
    acc.x += __shfl_xor_sync(0xffffffffu, acc.x, 16);
    acc.y += __shfl_xor_sync(0xffffffffu, acc.y, 16);
    acc.z += __shfl_xor_sync(0xffffffffu, acc.z, 16);
    acc.w += __shfl_xor_sync(0xffffffffu, acc.w, 16);

    if (kk == 0) {
        *(float4*)(g_AO + (size_t)bq * DMODEL + h * HDIM + dq * 4) = acc;
    }
}

// ---------------------------------------------------------------------------
// Launch: fused QKV projection -> attention -> output GEMM. Single stream,
// no allocation, no sync — graph-capturable.
// ---------------------------------------------------------------------------
extern "C" void kernel_launch(void* const* d_in, const int* in_sizes, int n_in,
                              void* d_out, int out_size)
{
    const float* Q  = (const float*)d_in[0];
    const float* K  = (const float*)d_in[1];
    const float* V  = (const float*)d_in[2];
    const float* tK = (const float*)d_in[3];
    const float* tV = (const float*)d_in[4];
    const float* Wq = (const float*)d_in[5];
    const float* bq = (const float*)d_in[6];
    const float* Wk = (const float*)d_in[7];
    const float* bk = (const float*)d_in[8];
    const float* Wv = (const float*)d_in[9];
    const float* bv = (const float*)d_in[10];
    const float* Wo = (const float*)d_in[11];
    const float* bo = (const float*)d_in[12];
    float* out = (float*)d_out;

    float *gQh, *gKh, *gVh, *gAO;
    cudaGetSymbolAddress((void**)&gQh, g_Qh);
    cudaGetSymbolAddress((void**)&gKh, g_Kh);
    cudaGetSymbolAddress((void**)&gVh, g_Vh);
    cudaGetSymbolAddress((void**)&gAO, g_AO);

    dim3 pgrid(ROWS / 64, DMODEL / 64, 3);
    gemm_proj3<<<pgrid, 256>>>(Q, K, V, Wq, bq, Wk, bk, Wv, bv, gQh, gKh, gVh);

    attn_kernel<<<ROWS, 256>>>(tK, tV);

    dim3 ogrid(ROWS / 64, DMODEL / 64);
    gemm_out<<<ogrid, 256>>>(gAO, Wo, bo, out);
}